// round 1
// baseline (speedup 1.0000x reference)
#include <cuda_runtime.h>

#define NB 4
#define NC 256
#define NO 256
#define NH 64
#define NW 64
#define NL 4096          // H*W
#define N9 36864         // 9*NL
#define NEPS 1e-5f

#define ATT_THREADS 512
#define ATT_SMEM_BYTES ((4096*4 + 36864) * 4)   // xs,t1,t2,ginv + fnum = 212992 B

// ---------------- scratch (static device globals; no runtime allocs) ----------------
static __device__ float g_y1[NB*NC*NL];
static __device__ float g_y2[NB*NC*NL];
static __device__ float g_pre[NB*NC*NL];
static __device__ float g_sc1[NC], g_sh1[NC];
static __device__ float g_sc2[NC], g_sh2[NC];
static __device__ float g_scF[NO], g_shF[NO];

// ---------------- dual 1x1-conv GEMM: y1/y2[b,o,l] = sum_c w[o,c]*x[b,c,l] + b[o] ----
__global__ __launch_bounds__(256) void dual_gemm_kernel(
    const float* __restrict__ x,
    const float* __restrict__ w1, const float* __restrict__ b1,
    const float* __restrict__ w2, const float* __restrict__ b2)
{
    __shared__ float xs[16][64];
    __shared__ float w1s[16][64];
    __shared__ float w2s[16][64];
    const int b  = blockIdx.z;
    const int o0 = blockIdx.y * 64;
    const int l0 = blockIdx.x * 64;
    const int tid = threadIdx.x;
    const int lt = (tid & 15) << 2;   // 0..60 within l-tile
    const int ot = (tid >> 4) << 2;   // 0..60 within o-tile
    const int rx = tid >> 4, cx = (tid & 15) << 2;  // x-tile load coords
    const int ow = tid >> 2, cw = (tid & 3) << 2;   // w-tile load coords
    const float* xb = x + (size_t)b * NC * NL;

    float a1[4][4], a2[4][4];
#pragma unroll
    for (int i = 0; i < 4; i++)
#pragma unroll
        for (int j = 0; j < 4; j++) { a1[i][j] = 0.f; a2[i][j] = 0.f; }

    for (int c0 = 0; c0 < NC; c0 += 16) {
        __syncthreads();
        *(float4*)&xs[rx][cx] = *(const float4*)&xb[(size_t)(c0 + rx) * NL + l0 + cx];
        float4 wa = *(const float4*)&w1[(size_t)(o0 + ow) * NC + c0 + cw];
        float4 wb = *(const float4*)&w2[(size_t)(o0 + ow) * NC + c0 + cw];
        w1s[cw+0][ow] = wa.x; w1s[cw+1][ow] = wa.y; w1s[cw+2][ow] = wa.z; w1s[cw+3][ow] = wa.w;
        w2s[cw+0][ow] = wb.x; w2s[cw+1][ow] = wb.y; w2s[cw+2][ow] = wb.z; w2s[cw+3][ow] = wb.w;
        __syncthreads();
#pragma unroll
        for (int cc = 0; cc < 16; cc++) {
            float4 xv = *(float4*)&xs[cc][lt];
            float4 u  = *(float4*)&w1s[cc][ot];
            float4 v  = *(float4*)&w2s[cc][ot];
            float xr[4] = {xv.x, xv.y, xv.z, xv.w};
            float ur[4] = {u.x, u.y, u.z, u.w};
            float vr[4] = {v.x, v.y, v.z, v.w};
#pragma unroll
            for (int i = 0; i < 4; i++)
#pragma unroll
                for (int j = 0; j < 4; j++) {
                    a1[i][j] = fmaf(ur[i], xr[j], a1[i][j]);
                    a2[i][j] = fmaf(vr[i], xr[j], a2[i][j]);
                }
        }
    }
#pragma unroll
    for (int i = 0; i < 4; i++) {
        const int o = o0 + ot + i;
        const float bb1 = b1[o], bb2 = b2[o];
        float4 s1 = make_float4(a1[i][0]+bb1, a1[i][1]+bb1, a1[i][2]+bb1, a1[i][3]+bb1);
        float4 s2 = make_float4(a2[i][0]+bb2, a2[i][1]+bb2, a2[i][2]+bb2, a2[i][3]+bb2);
        *(float4*)&g_y1[((size_t)b * NC + o) * NL + l0 + lt] = s1;
        *(float4*)&g_y2[((size_t)b * NC + o) * NL + l0 + lt] = s2;
    }
}

// ---------------- final 1x1-conv GEMM: out = wf @ pre + bf ----------------
__global__ __launch_bounds__(256) void final_gemm_kernel(
    const float* __restrict__ wf, const float* __restrict__ bf, float* __restrict__ out)
{
    __shared__ float xs[16][64];
    __shared__ float ws[16][64];
    const int b  = blockIdx.z;
    const int o0 = blockIdx.y * 64;
    const int l0 = blockIdx.x * 64;
    const int tid = threadIdx.x;
    const int lt = (tid & 15) << 2;
    const int ot = (tid >> 4) << 2;
    const int rx = tid >> 4, cx = (tid & 15) << 2;
    const int ow = tid >> 2, cw = (tid & 3) << 2;
    const float* xb = g_pre + (size_t)b * NC * NL;

    float a1[4][4];
#pragma unroll
    for (int i = 0; i < 4; i++)
#pragma unroll
        for (int j = 0; j < 4; j++) a1[i][j] = 0.f;

    for (int c0 = 0; c0 < NC; c0 += 16) {
        __syncthreads();
        *(float4*)&xs[rx][cx] = *(const float4*)&xb[(size_t)(c0 + rx) * NL + l0 + cx];
        float4 wa = *(const float4*)&wf[(size_t)(o0 + ow) * NC + c0 + cw];
        ws[cw+0][ow] = wa.x; ws[cw+1][ow] = wa.y; ws[cw+2][ow] = wa.z; ws[cw+3][ow] = wa.w;
        __syncthreads();
#pragma unroll
        for (int cc = 0; cc < 16; cc++) {
            float4 xv = *(float4*)&xs[cc][lt];
            float4 u  = *(float4*)&ws[cc][ot];
            float xr[4] = {xv.x, xv.y, xv.z, xv.w};
            float ur[4] = {u.x, u.y, u.z, u.w};
#pragma unroll
            for (int i = 0; i < 4; i++)
#pragma unroll
                for (int j = 0; j < 4; j++)
                    a1[i][j] = fmaf(ur[i], xr[j], a1[i][j]);
        }
    }
#pragma unroll
    for (int i = 0; i < 4; i++) {
        const int o = o0 + ot + i;
        const float bb = bf[o];
        float4 s1 = make_float4(a1[i][0]+bb, a1[i][1]+bb, a1[i][2]+bb, a1[i][3]+bb);
        *(float4*)&out[((size_t)b * NC + o) * NL + l0 + lt] = s1;
    }
}

// ---------------- BN stats: per-channel mean/var over (B,H,W), fold to scale/shift ----
__global__ __launch_bounds__(256) void bn_stats_kernel(
    int sel, const float* __restrict__ yext,
    const float* __restrict__ gw, const float* __restrict__ bw)
{
    const float* y = (sel == 0) ? g_y1 : (sel == 1) ? g_y2 : yext;
    float* sc = (sel == 0) ? g_sc1 : (sel == 1) ? g_sc2 : g_scF;
    float* sh = (sel == 0) ? g_sh1 : (sel == 1) ? g_sh2 : g_shF;
    const int ch = blockIdx.x;
    float s = 0.f, s2 = 0.f;
    for (int i = threadIdx.x; i < NB * NL; i += 256) {
        int b = i >> 12, l = i & (NL - 1);
        float v = y[((size_t)b * NC + ch) * NL + l];
        s += v; s2 += v * v;
    }
    __shared__ float r1[256], r2[256];
    r1[threadIdx.x] = s; r2[threadIdx.x] = s2;
    __syncthreads();
    for (int st = 128; st > 0; st >>= 1) {
        if (threadIdx.x < st) {
            r1[threadIdx.x] += r1[threadIdx.x + st];
            r2[threadIdx.x] += r2[threadIdx.x + st];
        }
        __syncthreads();
    }
    if (threadIdx.x == 0) {
        const float inv = 1.f / (float)(NB * NL);
        float mu  = r1[0] * inv;
        float var = r2[0] * inv - mu * mu;
        float r   = rsqrtf(var + NEPS) * gw[ch];
        sc[ch] = r;
        sh[ch] = bw[ch] - mu * r;
    }
}

// ---------------- scrambled-unfold attention (per-channel CTA, deterministic) --------
// flat n in [0,9L): ku_flat[n] = unfold(tri1)[p=n>>12, l=n&4095]; groups of 9 along n.
// pre[l3] = sum_{p=0..8} softmaxed(n=p*L+l3) * xu_flat(n)
__device__ __forceinline__ float nbv(const float* __restrict__ s, int n)
{
    const int p = n >> 12;           // 0..8
    const int l = n & (NL - 1);
    const int ii = (l >> 6) + p / 3 - 1;
    const int jj = (l & 63) + p % 3 - 1;
    return ((unsigned)ii < 64u && (unsigned)jj < 64u) ? s[(ii << 6) + jj] : 0.f;
}

__global__ __launch_bounds__(ATT_THREADS) void att_kernel(const float* __restrict__ x)
{
    extern __shared__ float sm[];
    float* xs = sm;             // 4096
    float* t1 = sm + 4096;      // 4096
    float* t2 = sm + 8192;      // 4096
    float* gv = sm + 12288;     // 4096 per-group 1/sum
    float* fn = sm + 16384;     // 36864 numerators e * xu

    const int bc = blockIdx.x;          // b*NC + c
    const int c  = bc & (NC - 1);
    const size_t base = (size_t)bc * NL;
    const float sc1 = g_sc1[c], sh1 = g_sh1[c];
    const float sc2 = g_sc2[c], sh2 = g_sh2[c];

    // load channel + apply BN+ReLU inline
    for (int i = threadIdx.x * 4; i < NL; i += ATT_THREADS * 4) {
        float4 xv = *(const float4*)&x[base + i];
        *(float4*)&xs[i] = xv;
        float4 a = *(const float4*)&g_y1[base + i];
        a.x = fmaxf(fmaf(a.x, sc1, sh1), 0.f);
        a.y = fmaxf(fmaf(a.y, sc1, sh1), 0.f);
        a.z = fmaxf(fmaf(a.z, sc1, sh1), 0.f);
        a.w = fmaxf(fmaf(a.w, sc1, sh1), 0.f);
        *(float4*)&t1[i] = a;
        float4 q = *(const float4*)&g_y2[base + i];
        q.x = fmaxf(fmaf(q.x, sc2, sh2), 0.f);
        q.y = fmaxf(fmaf(q.y, sc2, sh2), 0.f);
        q.z = fmaxf(fmaf(q.z, sc2, sh2), 0.f);
        q.w = fmaxf(fmaf(q.w, sc2, sh2), 0.f);
        *(float4*)&t2[i] = q;
    }
    __syncthreads();

    // phase 1: per softmax group (9 consecutive n), store numerators + 1/sum
    for (int g = threadIdx.x; g < NL; g += ATT_THREADS) {
        const int n0 = 9 * g;
        const float kuC = nbv(t1, n0 + 4);
        const float quC = nbv(t2, n0 + 4);
        float lg[9], xv[9];
        float m = -1e30f;
#pragma unroll
        for (int r = 0; r < 9; r++) {
            const int n = n0 + r;
            const float ku = nbv(t1, n);
            const float qu = nbv(t2, n);
            xv[r] = nbv(xs, n);
            lg[r] = ku * quC + kuC * qu;
            m = fmaxf(m, lg[r]);
        }
        float s = 0.f;
#pragma unroll
        for (int r = 0; r < 9; r++) {
            const float e = __expf(lg[r] - m);
            s += e;
            fn[n0 + r] = e * xv[r];
        }
        gv[g] = 1.f / s;
    }
    __syncthreads();

    // phase 2: pre[l3] = sum_p fn[p*L + l3] * gv[(p*L+l3)/9]   (conflict-free)
    for (int l = threadIdx.x; l < NL; l += ATT_THREADS) {
        float acc = 0.f;
#pragma unroll
        for (int p = 0; p < 9; p++) {
            const int n = (p << 12) + l;
            acc += fn[n] * gv[n / 9];
        }
        g_pre[base + l] = acc;
    }
}

// ---------------- final in-place BN + ReLU on d_out ----------------
__global__ __launch_bounds__(256) void bn_relu_kernel(float* __restrict__ y)
{
    const int i4 = (blockIdx.x * 256 + threadIdx.x) * 4;
    const int ch = (i4 >> 12) & (NO - 1);
    const float sc = g_scF[ch], sh = g_shF[ch];
    float4 v = *(float4*)&y[i4];
    v.x = fmaxf(fmaf(v.x, sc, sh), 0.f);
    v.y = fmaxf(fmaf(v.y, sc, sh), 0.f);
    v.z = fmaxf(fmaf(v.z, sc, sh), 0.f);
    v.w = fmaxf(fmaf(v.w, sc, sh), 0.f);
    *(float4*)&y[i4] = v;
}

// ---------------- launch ----------------
extern "C" void kernel_launch(void* const* d_in, const int* in_sizes, int n_in,
                              void* d_out, int out_size)
{
    (void)in_sizes; (void)n_in; (void)out_size;
    const float* x   = (const float*)d_in[0];
    const float* w1  = (const float*)d_in[1];
    const float* b1  = (const float*)d_in[2];
    const float* g1  = (const float*)d_in[3];
    const float* be1 = (const float*)d_in[4];
    const float* w2  = (const float*)d_in[5];
    const float* b2  = (const float*)d_in[6];
    const float* g2  = (const float*)d_in[7];
    const float* be2 = (const float*)d_in[8];
    const float* wf  = (const float*)d_in[9];
    const float* bf  = (const float*)d_in[10];
    const float* gf  = (const float*)d_in[11];
    const float* bef = (const float*)d_in[12];
    float* out = (float*)d_out;

    cudaFuncSetAttribute(att_kernel, cudaFuncAttributeMaxDynamicSharedMemorySize,
                         ATT_SMEM_BYTES);

    dim3 gg(NL / 64, NO / 64, NB);
    dual_gemm_kernel<<<gg, 256>>>(x, w1, b1, w2, b2);
    bn_stats_kernel<<<NC, 256>>>(0, nullptr, g1, be1);
    bn_stats_kernel<<<NC, 256>>>(1, nullptr, g2, be2);
    att_kernel<<<NB * NC, ATT_THREADS, ATT_SMEM_BYTES>>>(x);
    final_gemm_kernel<<<gg, 256>>>(wf, bf, out);
    bn_stats_kernel<<<NC, 256>>>(2, out, gf, bef);
    bn_relu_kernel<<<(NB * NC * NL) / (256 * 4), 256>>>(out);
}

// round 2
// speedup vs baseline: 1.0877x; 1.0877x over previous
#include <cuda_runtime.h>

#define NB 4
#define NC 256
#define NO 256
#define NL 4096          // H*W
#define NEPS 1e-5f

#define ATT_THREADS 1024
#define ATT_SMEM_BYTES ((4096*4 + 36864) * 4)   // xs,t1,t2,ginv + fnum = 212992 B

// packed fp32x2 helpers (Blackwell FFMA2 — only reachable via PTX)
#define FMA_F32X2(d, a, b, c) \
    asm("fma.rn.f32x2 %0, %1, %2, %3;" : "=l"(d) : "l"(a), "l"(b), "l"(c))
#define PACK_DUP(d, f) \
    asm("mov.b64 %0, {%1, %1};" : "=l"(d) : "f"(f))

// ---------------- scratch (static device globals; no runtime allocs) ----------------
static __device__ float g_y1[NB*NC*NL];
static __device__ float g_y2[NB*NC*NL];
static __device__ float g_pre[NB*NC*NL];
static __device__ float g_sc1[NC], g_sh1[NC];
static __device__ float g_sc2[NC], g_sh2[NC];
static __device__ float g_scF[NO], g_shF[NO];

// ---------------- dual 1x1-conv GEMM (FFMA2): y1/y2 = w1/w2 @ x + b ----------------
__global__ __launch_bounds__(256) void dual_gemm_kernel(
    const float* __restrict__ x,
    const float* __restrict__ w1, const float* __restrict__ b1,
    const float* __restrict__ w2, const float* __restrict__ b2)
{
    __shared__ float xs[16][64];
    __shared__ float w1s[16][64];   // [c][o] — o contiguous => packed pairs load free
    __shared__ float w2s[16][64];
    const int b  = blockIdx.z;
    const int o0 = blockIdx.y * 64;
    const int l0 = blockIdx.x * 64;
    const int tid = threadIdx.x;
    const int lt = (tid & 15) << 2;   // l within tile
    const int ot = (tid >> 4) << 2;   // o within tile
    const int rx = tid >> 4, cx = (tid & 15) << 2;
    const int ow = tid >> 2, cw = (tid & 3) << 2;
    const float* xb = x + (size_t)b * NC * NL;

    // accumulators: packed pairs along o: a[mat][ip][j], ip in {0,1} -> o=ot+2ip,(+1)
    unsigned long long a1[2][4], a2[2][4];
#pragma unroll
    for (int i = 0; i < 2; i++)
#pragma unroll
        for (int j = 0; j < 4; j++) { a1[i][j] = 0ull; a2[i][j] = 0ull; }

    for (int c0 = 0; c0 < NC; c0 += 16) {
        __syncthreads();
        *(float4*)&xs[rx][cx] = *(const float4*)&xb[(size_t)(c0 + rx) * NL + l0 + cx];
        float4 wa = *(const float4*)&w1[(size_t)(o0 + ow) * NC + c0 + cw];
        float4 wb = *(const float4*)&w2[(size_t)(o0 + ow) * NC + c0 + cw];
        w1s[cw+0][ow] = wa.x; w1s[cw+1][ow] = wa.y; w1s[cw+2][ow] = wa.z; w1s[cw+3][ow] = wa.w;
        w2s[cw+0][ow] = wb.x; w2s[cw+1][ow] = wb.y; w2s[cw+2][ow] = wb.z; w2s[cw+3][ow] = wb.w;
        __syncthreads();
#pragma unroll
        for (int cc = 0; cc < 16; cc++) {
            float4 xv = *(float4*)&xs[cc][lt];
            ulonglong2 u2 = *(ulonglong2*)&w1s[cc][ot];   // (w[ot],w[ot+1]),(w[ot+2],w[ot+3])
            ulonglong2 v2 = *(ulonglong2*)&w2s[cc][ot];
            unsigned long long xd[4];
            PACK_DUP(xd[0], xv.x); PACK_DUP(xd[1], xv.y);
            PACK_DUP(xd[2], xv.z); PACK_DUP(xd[3], xv.w);
#pragma unroll
            for (int j = 0; j < 4; j++) {
                FMA_F32X2(a1[0][j], u2.x, xd[j], a1[0][j]);
                FMA_F32X2(a1[1][j], u2.y, xd[j], a1[1][j]);
                FMA_F32X2(a2[0][j], v2.x, xd[j], a2[0][j]);
                FMA_F32X2(a2[1][j], v2.y, xd[j], a2[1][j]);
            }
        }
    }
    // unpack: a[ip][j] holds (o=ot+2ip, o=ot+2ip+1) for column lt+j
#pragma unroll
    for (int ip = 0; ip < 2; ip++) {
#pragma unroll
        for (int half = 0; half < 2; half++) {
            const int o = o0 + ot + 2*ip + half;
            const float bb1 = b1[o], bb2 = b2[o];
            float r1[4], r2[4];
#pragma unroll
            for (int j = 0; j < 4; j++) {
                float2 p1 = *(float2*)&a1[ip][j];
                float2 p2 = *(float2*)&a2[ip][j];
                r1[j] = (half ? p1.y : p1.x) + bb1;
                r2[j] = (half ? p2.y : p2.x) + bb2;
            }
            *(float4*)&g_y1[((size_t)b * NC + o) * NL + l0 + lt] =
                make_float4(r1[0], r1[1], r1[2], r1[3]);
            *(float4*)&g_y2[((size_t)b * NC + o) * NL + l0 + lt] =
                make_float4(r2[0], r2[1], r2[2], r2[3]);
        }
    }
}

// ---------------- final 1x1-conv GEMM (FFMA2): out = wf @ pre + bf ----------------
__global__ __launch_bounds__(256) void final_gemm_kernel(
    const float* __restrict__ wf, const float* __restrict__ bf, float* __restrict__ out)
{
    __shared__ float xs[16][64];
    __shared__ float ws[16][64];
    const int b  = blockIdx.z;
    const int o0 = blockIdx.y * 64;
    const int l0 = blockIdx.x * 64;
    const int tid = threadIdx.x;
    const int lt = (tid & 15) << 2;
    const int ot = (tid >> 4) << 2;
    const int rx = tid >> 4, cx = (tid & 15) << 2;
    const int ow = tid >> 2, cw = (tid & 3) << 2;
    const float* xb = g_pre + (size_t)b * NC * NL;

    unsigned long long a1[2][4];
#pragma unroll
    for (int i = 0; i < 2; i++)
#pragma unroll
        for (int j = 0; j < 4; j++) a1[i][j] = 0ull;

    for (int c0 = 0; c0 < NC; c0 += 16) {
        __syncthreads();
        *(float4*)&xs[rx][cx] = *(const float4*)&xb[(size_t)(c0 + rx) * NL + l0 + cx];
        float4 wa = *(const float4*)&wf[(size_t)(o0 + ow) * NC + c0 + cw];
        ws[cw+0][ow] = wa.x; ws[cw+1][ow] = wa.y; ws[cw+2][ow] = wa.z; ws[cw+3][ow] = wa.w;
        __syncthreads();
#pragma unroll
        for (int cc = 0; cc < 16; cc++) {
            float4 xv = *(float4*)&xs[cc][lt];
            ulonglong2 u2 = *(ulonglong2*)&ws[cc][ot];
            unsigned long long xd[4];
            PACK_DUP(xd[0], xv.x); PACK_DUP(xd[1], xv.y);
            PACK_DUP(xd[2], xv.z); PACK_DUP(xd[3], xv.w);
#pragma unroll
            for (int j = 0; j < 4; j++) {
                FMA_F32X2(a1[0][j], u2.x, xd[j], a1[0][j]);
                FMA_F32X2(a1[1][j], u2.y, xd[j], a1[1][j]);
            }
        }
    }
#pragma unroll
    for (int ip = 0; ip < 2; ip++) {
#pragma unroll
        for (int half = 0; half < 2; half++) {
            const int o = o0 + ot + 2*ip + half;
            const float bb = bf[o];
            float r1[4];
#pragma unroll
            for (int j = 0; j < 4; j++) {
                float2 p1 = *(float2*)&a1[ip][j];
                r1[j] = (half ? p1.y : p1.x) + bb;
            }
            *(float4*)&out[((size_t)b * NC + o) * NL + l0 + lt] =
                make_float4(r1[0], r1[1], r1[2], r1[3]);
        }
    }
}

// ---------------- BN stats: per-channel mean/var over (B,H,W) -> scale/shift --------
__global__ __launch_bounds__(256) void bn_stats_kernel(
    int sel, const float* __restrict__ yext,
    const float* __restrict__ gw, const float* __restrict__ bw)
{
    const float* y = (sel == 0) ? g_y1 : (sel == 1) ? g_y2 : yext;
    float* sc = (sel == 0) ? g_sc1 : (sel == 1) ? g_sc2 : g_scF;
    float* sh = (sel == 0) ? g_sh1 : (sel == 1) ? g_sh2 : g_shF;
    const int ch = blockIdx.x;
    float s = 0.f, s2 = 0.f;
    for (int i = threadIdx.x; i < NB * NL; i += 256) {
        int b = i >> 12, l = i & (NL - 1);
        float v = y[((size_t)b * NC + ch) * NL + l];
        s += v; s2 += v * v;
    }
    __shared__ float r1[256], r2[256];
    r1[threadIdx.x] = s; r2[threadIdx.x] = s2;
    __syncthreads();
    for (int st = 128; st > 0; st >>= 1) {
        if (threadIdx.x < st) {
            r1[threadIdx.x] += r1[threadIdx.x + st];
            r2[threadIdx.x] += r2[threadIdx.x + st];
        }
        __syncthreads();
    }
    if (threadIdx.x == 0) {
        const float inv = 1.f / (float)(NB * NL);
        float mu  = r1[0] * inv;
        float var = r2[0] * inv - mu * mu;
        float r   = rsqrtf(var + NEPS) * gw[ch];
        sc[ch] = r;
        sh[ch] = bw[ch] - mu * r;
    }
}

// ---------------- scrambled-unfold attention (per-channel CTA, deterministic) --------
// flat n in [0,9L): value(s,n) = s_padded[row(l)+p/3-1, col(l)+p%3-1], p=n>>12, l=n&4095.
// Key identity: smem index = l + 64*(p/3-1) + (p%3-1); one address + one predicate
// shared by all three streams (t1, t2, xs).
__global__ __launch_bounds__(ATT_THREADS) void att_kernel(const float* __restrict__ x)
{
    extern __shared__ float sm[];
    float* xs = sm;             // 4096
    float* t1 = sm + 4096;      // 4096
    float* t2 = sm + 8192;      // 4096
    float* gv = sm + 12288;     // 4096 per-group 1/sum
    float* fn = sm + 16384;     // 36864 numerators e * xu

    const int bc = blockIdx.x;          // b*NC + c
    const int c  = bc & (NC - 1);
    const size_t base = (size_t)bc * NL;
    const float sc1 = g_sc1[c], sh1 = g_sh1[c];
    const float sc2 = g_sc2[c], sh2 = g_sh2[c];

    // load channel + apply BN+ReLU inline
    for (int i = threadIdx.x * 4; i < NL; i += ATT_THREADS * 4) {
        float4 xv = *(const float4*)&x[base + i];
        *(float4*)&xs[i] = xv;
        float4 a = *(const float4*)&g_y1[base + i];
        a.x = fmaxf(fmaf(a.x, sc1, sh1), 0.f);
        a.y = fmaxf(fmaf(a.y, sc1, sh1), 0.f);
        a.z = fmaxf(fmaf(a.z, sc1, sh1), 0.f);
        a.w = fmaxf(fmaf(a.w, sc1, sh1), 0.f);
        *(float4*)&t1[i] = a;
        float4 q = *(const float4*)&g_y2[base + i];
        q.x = fmaxf(fmaf(q.x, sc2, sh2), 0.f);
        q.y = fmaxf(fmaf(q.y, sc2, sh2), 0.f);
        q.z = fmaxf(fmaf(q.z, sc2, sh2), 0.f);
        q.w = fmaxf(fmaf(q.w, sc2, sh2), 0.f);
        *(float4*)&t2[i] = q;
    }
    __syncthreads();

    // phase 1: per softmax group (9 consecutive n): shared addressing for 3 streams
    for (int g = threadIdx.x; g < NL; g += ATT_THREADS) {
        const int n0 = 9 * g;
        float ku[9], qu[9], xv[9];
#pragma unroll
        for (int r = 0; r < 9; r++) {
            const int n  = n0 + r;
            const int p  = n >> 12;
            const int l  = n & (NL - 1);
            const int di = (p * 171) >> 9;      // p/3
            const int dj = p - 3 * di;          // p%3
            const int ii = (l >> 6) + di - 1;
            const int jj = (l & 63) + dj - 1;
            const bool ok = ((unsigned)ii < 64u) && ((unsigned)jj < 64u);
            const int idx = ok ? (l + ((di - 1) << 6) + (dj - 1)) : 0;
            const float k0 = t1[idx];
            const float q0 = t2[idx];
            const float x0 = xs[idx];
            ku[r] = ok ? k0 : 0.f;
            qu[r] = ok ? q0 : 0.f;
            xv[r] = ok ? x0 : 0.f;
        }
        const float kuC = ku[4], quC = qu[4];
        float lg[9];
        float m = -1e30f;
#pragma unroll
        for (int r = 0; r < 9; r++) {
            lg[r] = ku[r] * quC + kuC * qu[r];
            m = fmaxf(m, lg[r]);
        }
        float s = 0.f;
#pragma unroll
        for (int r = 0; r < 9; r++) {
            const float e = __expf(lg[r] - m);
            s += e;
            fn[n0 + r] = e * xv[r];
        }
        gv[g] = 1.f / s;
    }
    __syncthreads();

    // phase 2: pre[l3] = sum_p fn[p*L + l3] * gv[(p*L+l3)/9]
    for (int l = threadIdx.x; l < NL; l += ATT_THREADS) {
        float acc = 0.f;
#pragma unroll
        for (int p = 0; p < 9; p++) {
            const int n = (p << 12) + l;
            acc += fn[n] * gv[n / 9];
        }
        g_pre[base + l] = acc;
    }
}

// ---------------- final in-place BN + ReLU on d_out ----------------
__global__ __launch_bounds__(256) void bn_relu_kernel(float* __restrict__ y)
{
    const int i4 = (blockIdx.x * 256 + threadIdx.x) * 4;
    const int ch = (i4 >> 12) & (NO - 1);
    const float sc = g_scF[ch], sh = g_shF[ch];
    float4 v = *(float4*)&y[i4];
    v.x = fmaxf(fmaf(v.x, sc, sh), 0.f);
    v.y = fmaxf(fmaf(v.y, sc, sh), 0.f);
    v.z = fmaxf(fmaf(v.z, sc, sh), 0.f);
    v.w = fmaxf(fmaf(v.w, sc, sh), 0.f);
    *(float4*)&y[i4] = v;
}

// ---------------- launch ----------------
extern "C" void kernel_launch(void* const* d_in, const int* in_sizes, int n_in,
                              void* d_out, int out_size)
{
    (void)in_sizes; (void)n_in; (void)out_size;
    const float* x   = (const float*)d_in[0];
    const float* w1  = (const float*)d_in[1];
    const float* b1  = (const float*)d_in[2];
    const float* g1  = (const float*)d_in[3];
    const float* be1 = (const float*)d_in[4];
    const float* w2  = (const float*)d_in[5];
    const float* b2  = (const float*)d_in[6];
    const float* g2  = (const float*)d_in[7];
    const float* be2 = (const float*)d_in[8];
    const float* wf  = (const float*)d_in[9];
    const float* bf  = (const float*)d_in[10];
    const float* gf  = (const float*)d_in[11];
    const float* bef = (const float*)d_in[12];
    float* out = (float*)d_out;

    cudaFuncSetAttribute(att_kernel, cudaFuncAttributeMaxDynamicSharedMemorySize,
                         ATT_SMEM_BYTES);

    dim3 gg(NL / 64, NO / 64, NB);
    dual_gemm_kernel<<<gg, 256>>>(x, w1, b1, w2, b2);
    bn_stats_kernel<<<NC, 256>>>(0, nullptr, g1, be1);
    bn_stats_kernel<<<NC, 256>>>(1, nullptr, g2, be2);
    att_kernel<<<NB * NC, ATT_THREADS, ATT_SMEM_BYTES>>>(x);
    final_gemm_kernel<<<gg, 256>>>(wf, bf, out);
    bn_stats_kernel<<<NC, 256>>>(2, out, gf, bef);
    bn_relu_kernel<<<(NB * NC * NL) / (256 * 4), 256>>>(out);
}

// round 3
// speedup vs baseline: 1.0901x; 1.0022x over previous
#include <cuda_runtime.h>

#define NB 4
#define NC 256
#define NO 256
#define NL 4096          // H*W
#define NEPS 1e-5f
#define LOG2E 1.4426950408889634f

#define ATT_THREADS 1024
// smem floats: fn 36864 | t12 8712 (66x66 float2) | xs 4356 | gv 4096  = 54028 floats
#define ATT_F_FN   0
#define ATT_F_T12  36864
#define ATT_F_XS   (36864 + 8712)
#define ATT_F_GV   (36864 + 8712 + 4356)
#define ATT_SMEM_BYTES ((36864 + 8712 + 4356 + 4096) * 4)

// packed fp32x2 helpers (Blackwell FFMA2 — only reachable via PTX)
#define FMA_F32X2(d, a, b, c) \
    asm("fma.rn.f32x2 %0, %1, %2, %3;" : "=l"(d) : "l"(a), "l"(b), "l"(c))
#define PACK_DUP(d, f) \
    asm("mov.b64 %0, {%1, %1};" : "=l"(d) : "f"(f))
#define EX2_APPROX(d, a) \
    asm("ex2.approx.ftz.f32 %0, %1;" : "=f"(d) : "f"(a))

// ---------------- scratch (static device globals; no runtime allocs) ----------------
static __device__ float g_y1[NB*NC*NL];
static __device__ float g_y2[NB*NC*NL];
static __device__ float g_pre[NB*NC*NL];
static __device__ float g_sc1[NC], g_sh1[NC];
static __device__ float g_sc2[NC], g_sh2[NC];
static __device__ float g_scF[NO], g_shF[NO];

// ---------------- dual 1x1-conv GEMM (FFMA2, double-buffered) ----------------
__global__ __launch_bounds__(256) void dual_gemm_kernel(
    const float* __restrict__ x,
    const float* __restrict__ w1, const float* __restrict__ b1,
    const float* __restrict__ w2, const float* __restrict__ b2)
{
    __shared__ float xs[2][16][64];
    __shared__ float w1s[2][16][64];   // [c][o]: o contiguous => packed pairs load free
    __shared__ float w2s[2][16][64];
    const int b  = blockIdx.z;
    const int o0 = blockIdx.y * 64;
    const int l0 = blockIdx.x * 64;
    const int tid = threadIdx.x;
    const int lt = (tid & 15) << 2;
    const int ot = (tid >> 4) << 2;
    const int rx = tid >> 4, cx = (tid & 15) << 2;
    const int ow = tid >> 2, cw = (tid & 3) << 2;
    const float* xb = x + (size_t)b * NC * NL;

    unsigned long long a1[2][4], a2[2][4];
#pragma unroll
    for (int i = 0; i < 2; i++)
#pragma unroll
        for (int j = 0; j < 4; j++) { a1[i][j] = 0ull; a2[i][j] = 0ull; }

    float4 xg = *(const float4*)&xb[(size_t)rx * NL + l0 + cx];
    float4 wg1 = *(const float4*)&w1[(size_t)(o0 + ow) * NC + cw];
    float4 wg2 = *(const float4*)&w2[(size_t)(o0 + ow) * NC + cw];
    *(float4*)&xs[0][rx][cx] = xg;
    w1s[0][cw+0][ow] = wg1.x; w1s[0][cw+1][ow] = wg1.y;
    w1s[0][cw+2][ow] = wg1.z; w1s[0][cw+3][ow] = wg1.w;
    w2s[0][cw+0][ow] = wg2.x; w2s[0][cw+1][ow] = wg2.y;
    w2s[0][cw+2][ow] = wg2.z; w2s[0][cw+3][ow] = wg2.w;
    __syncthreads();

    int p = 0;
#pragma unroll 1
    for (int it = 0; it < 16; ++it) {
        if (it < 15) {
            const int c0n = (it + 1) * 16;
            xg  = *(const float4*)&xb[(size_t)(c0n + rx) * NL + l0 + cx];
            wg1 = *(const float4*)&w1[(size_t)(o0 + ow) * NC + c0n + cw];
            wg2 = *(const float4*)&w2[(size_t)(o0 + ow) * NC + c0n + cw];
        }
#pragma unroll
        for (int cc = 0; cc < 16; cc++) {
            float4 xv = *(float4*)&xs[p][cc][lt];
            ulonglong2 u2 = *(ulonglong2*)&w1s[p][cc][ot];
            ulonglong2 v2 = *(ulonglong2*)&w2s[p][cc][ot];
            unsigned long long xd[4];
            PACK_DUP(xd[0], xv.x); PACK_DUP(xd[1], xv.y);
            PACK_DUP(xd[2], xv.z); PACK_DUP(xd[3], xv.w);
#pragma unroll
            for (int j = 0; j < 4; j++) {
                FMA_F32X2(a1[0][j], u2.x, xd[j], a1[0][j]);
                FMA_F32X2(a1[1][j], u2.y, xd[j], a1[1][j]);
                FMA_F32X2(a2[0][j], v2.x, xd[j], a2[0][j]);
                FMA_F32X2(a2[1][j], v2.y, xd[j], a2[1][j]);
            }
        }
        if (it < 15) {
            const int q = p ^ 1;
            *(float4*)&xs[q][rx][cx] = xg;
            w1s[q][cw+0][ow] = wg1.x; w1s[q][cw+1][ow] = wg1.y;
            w1s[q][cw+2][ow] = wg1.z; w1s[q][cw+3][ow] = wg1.w;
            w2s[q][cw+0][ow] = wg2.x; w2s[q][cw+1][ow] = wg2.y;
            w2s[q][cw+2][ow] = wg2.z; w2s[q][cw+3][ow] = wg2.w;
            __syncthreads();
            p = q;
        }
    }
#pragma unroll
    for (int ip = 0; ip < 2; ip++) {
#pragma unroll
        for (int half = 0; half < 2; half++) {
            const int o = o0 + ot + 2*ip + half;
            const float bb1 = b1[o], bb2 = b2[o];
            float r1[4], r2[4];
#pragma unroll
            for (int j = 0; j < 4; j++) {
                float2 p1 = *(float2*)&a1[ip][j];
                float2 p2 = *(float2*)&a2[ip][j];
                r1[j] = (half ? p1.y : p1.x) + bb1;
                r2[j] = (half ? p2.y : p2.x) + bb2;
            }
            *(float4*)&g_y1[((size_t)b * NC + o) * NL + l0 + lt] =
                make_float4(r1[0], r1[1], r1[2], r1[3]);
            *(float4*)&g_y2[((size_t)b * NC + o) * NL + l0 + lt] =
                make_float4(r2[0], r2[1], r2[2], r2[3]);
        }
    }
}

// ---------------- final 1x1-conv GEMM (FFMA2, double-buffered) ----------------
__global__ __launch_bounds__(256) void final_gemm_kernel(
    const float* __restrict__ wf, const float* __restrict__ bf, float* __restrict__ out)
{
    __shared__ float xs[2][16][64];
    __shared__ float ws[2][16][64];
    const int b  = blockIdx.z;
    const int o0 = blockIdx.y * 64;
    const int l0 = blockIdx.x * 64;
    const int tid = threadIdx.x;
    const int lt = (tid & 15) << 2;
    const int ot = (tid >> 4) << 2;
    const int rx = tid >> 4, cx = (tid & 15) << 2;
    const int ow = tid >> 2, cw = (tid & 3) << 2;
    const float* xb = g_pre + (size_t)b * NC * NL;

    unsigned long long a1[2][4];
#pragma unroll
    for (int i = 0; i < 2; i++)
#pragma unroll
        for (int j = 0; j < 4; j++) a1[i][j] = 0ull;

    float4 xg = *(const float4*)&xb[(size_t)rx * NL + l0 + cx];
    float4 wg = *(const float4*)&wf[(size_t)(o0 + ow) * NC + cw];
    *(float4*)&xs[0][rx][cx] = xg;
    ws[0][cw+0][ow] = wg.x; ws[0][cw+1][ow] = wg.y;
    ws[0][cw+2][ow] = wg.z; ws[0][cw+3][ow] = wg.w;
    __syncthreads();

    int p = 0;
#pragma unroll 1
    for (int it = 0; it < 16; ++it) {
        if (it < 15) {
            const int c0n = (it + 1) * 16;
            xg = *(const float4*)&xb[(size_t)(c0n + rx) * NL + l0 + cx];
            wg = *(const float4*)&wf[(size_t)(o0 + ow) * NC + c0n + cw];
        }
#pragma unroll
        for (int cc = 0; cc < 16; cc++) {
            float4 xv = *(float4*)&xs[p][cc][lt];
            ulonglong2 u2 = *(ulonglong2*)&ws[p][cc][ot];
            unsigned long long xd[4];
            PACK_DUP(xd[0], xv.x); PACK_DUP(xd[1], xv.y);
            PACK_DUP(xd[2], xv.z); PACK_DUP(xd[3], xv.w);
#pragma unroll
            for (int j = 0; j < 4; j++) {
                FMA_F32X2(a1[0][j], u2.x, xd[j], a1[0][j]);
                FMA_F32X2(a1[1][j], u2.y, xd[j], a1[1][j]);
            }
        }
        if (it < 15) {
            const int q = p ^ 1;
            *(float4*)&xs[q][rx][cx] = xg;
            ws[q][cw+0][ow] = wg.x; ws[q][cw+1][ow] = wg.y;
            ws[q][cw+2][ow] = wg.z; ws[q][cw+3][ow] = wg.w;
            __syncthreads();
            p = q;
        }
    }
#pragma unroll
    for (int ip = 0; ip < 2; ip++) {
#pragma unroll
        for (int half = 0; half < 2; half++) {
            const int o = o0 + ot + 2*ip + half;
            const float bb = bf[o];
            float r1[4];
#pragma unroll
            for (int j = 0; j < 4; j++) {
                float2 p1 = *(float2*)&a1[ip][j];
                r1[j] = (half ? p1.y : p1.x) + bb;
            }
            *(float4*)&out[((size_t)b * NC + o) * NL + l0 + lt] =
                make_float4(r1[0], r1[1], r1[2], r1[3]);
        }
    }
}

// ---------------- BN stats: per-channel mean/var over (B,H,W) -> scale/shift --------
__global__ __launch_bounds__(256) void bn_stats_kernel(
    int sel, const float* __restrict__ yext,
    const float* __restrict__ gw, const float* __restrict__ bw)
{
    const float* y = (sel == 0) ? g_y1 : (sel == 1) ? g_y2 : yext;
    float* sc = (sel == 0) ? g_sc1 : (sel == 1) ? g_sc2 : g_scF;
    float* sh = (sel == 0) ? g_sh1 : (sel == 1) ? g_sh2 : g_shF;
    const int ch = blockIdx.x;
    float s = 0.f, s2 = 0.f;
    for (int i = threadIdx.x; i < NB * NL; i += 256) {
        int b = i >> 12, l = i & (NL - 1);
        float v = y[((size_t)b * NC + ch) * NL + l];
        s += v; s2 += v * v;
    }
    __shared__ float r1[256], r2[256];
    r1[threadIdx.x] = s; r2[threadIdx.x] = s2;
    __syncthreads();
    for (int st = 128; st > 0; st >>= 1) {
        if (threadIdx.x < st) {
            r1[threadIdx.x] += r1[threadIdx.x + st];
            r2[threadIdx.x] += r2[threadIdx.x + st];
        }
        __syncthreads();
    }
    if (threadIdx.x == 0) {
        const float inv = 1.f / (float)(NB * NL);
        float mu  = r1[0] * inv;
        float var = r2[0] * inv - mu * mu;
        float r   = rsqrtf(var + NEPS) * gw[ch];
        sc[ch] = r;
        sh[ch] = bw[ch] - mu * r;
    }
}

// ---------------- scrambled-unfold attention (padded halo planes) --------------------
// tap value for flat n = p*4096 + l lives at padded-plane cell
//   idx = (l>>6)*66 + (l&63) + C,  C = 66*(p/3) + (p%3)  (minus 4224 if l crossed 4096)
// halo cells are exact zeros => no bounds checks, no selects.
__global__ __launch_bounds__(ATT_THREADS) void att_kernel(const float* __restrict__ x)
{
    extern __shared__ float sm[];
    float* fn  = sm + ATT_F_FN;    // 36864 numerators e * xu
    float* t12 = sm + ATT_F_T12;   // 66x66 interleaved (tri1, tri2) float2
    float* xs  = sm + ATT_F_XS;    // 66x66 padded x plane
    float* gv  = sm + ATT_F_GV;    // 4096 per-group 1/sum

    const int bc = blockIdx.x;          // b*NC + c
    const int c  = bc & (NC - 1);
    const size_t base = (size_t)bc * NL;
    const float sc1 = g_sc1[c], sh1 = g_sh1[c];
    const float sc2 = g_sc2[c], sh2 = g_sh2[c];

    // zero halo (whole planes), then fill interior with BN+ReLU applied
    for (int i = threadIdx.x; i < 4356; i += ATT_THREADS) xs[i] = 0.f;
    for (int i = threadIdx.x; i < 8712; i += ATT_THREADS) t12[i] = 0.f;
    __syncthreads();

    for (int l4 = threadIdx.x * 4; l4 < NL; l4 += ATT_THREADS * 4) {
        float4 xv = *(const float4*)&x[base + l4];
        float4 a  = *(const float4*)&g_y1[base + l4];
        float4 q  = *(const float4*)&g_y2[base + l4];
        const int pidx = (l4 >> 6) * 66 + (l4 & 63) + 67;  // (row+1)*66 + col+1
        xs[pidx+0] = xv.x; xs[pidx+1] = xv.y; xs[pidx+2] = xv.z; xs[pidx+3] = xv.w;
        float t1v[4] = {
            fmaxf(fmaf(a.x, sc1, sh1), 0.f), fmaxf(fmaf(a.y, sc1, sh1), 0.f),
            fmaxf(fmaf(a.z, sc1, sh1), 0.f), fmaxf(fmaf(a.w, sc1, sh1), 0.f) };
        float t2v[4] = {
            fmaxf(fmaf(q.x, sc2, sh2), 0.f), fmaxf(fmaf(q.y, sc2, sh2), 0.f),
            fmaxf(fmaf(q.z, sc2, sh2), 0.f), fmaxf(fmaf(q.w, sc2, sh2), 0.f) };
#pragma unroll
        for (int j = 0; j < 4; j++)
            *(float2*)&t12[2 * (pidx + j)] = make_float2(t1v[j], t2v[j]);
    }
    __syncthreads();

    // phase 1: per softmax group (9 consecutive n)
    for (int g = threadIdx.x; g < NL; g += ATT_THREADS) {
        const int n0 = 9 * g;
        const int p0 = n0 >> 12;
        const int l0 = n0 & (NL - 1);
        const int di0 = (p0 * 171) >> 9, dj0 = p0 - 3 * di0;
        const int p1 = p0 + 1;
        const int di1 = (p1 * 171) >> 9, dj1 = p1 - 3 * di1;
        const int C0 = di0 * 66 + dj0;
        const int C1 = di1 * 66 + dj1 - 4224;   // fold the l-4096 row shift
        float ku[9], qu[9], xv[9];
#pragma unroll
        for (int r = 0; r < 9; r++) {
            const int l = l0 + r;
            const int C = (l >> 12) ? C1 : C0;
            const int idx = (l >> 6) * 66 + (l & 63) + C;
            const float2 kq = *(const float2*)&t12[2 * idx];
            ku[r] = kq.x; qu[r] = kq.y;
            xv[r] = xs[idx];
        }
        const float quC = qu[4] * LOG2E;
        const float kuC = ku[4] * LOG2E;
        float lg[9];
        float m = -1e30f;
#pragma unroll
        for (int r = 0; r < 9; r++) {
            lg[r] = fmaf(ku[r], quC, kuC * qu[r]);
            m = fmaxf(m, lg[r]);
        }
        float s = 0.f;
#pragma unroll
        for (int r = 0; r < 9; r++) {
            float e; EX2_APPROX(e, lg[r] - m);
            s += e;
            fn[n0 + r] = e * xv[r];
        }
        gv[g] = 1.f / s;
    }
    __syncthreads();

    // phase 2: pre[l] = sum_p fn[p*L + l] * gv[(p*L+l)/9]
    for (int l = threadIdx.x; l < NL; l += ATT_THREADS) {
        float acc = 0.f;
#pragma unroll
        for (int p = 0; p < 9; p++) {
            const unsigned n = (p << 12) + l;
            const unsigned gidx = __umulhi(n, 0x38E38E39u) >> 1;   // n/9
            acc += fn[n] * gv[gidx];
        }
        g_pre[base + l] = acc;
    }
}

// ---------------- final in-place BN + ReLU on d_out ----------------
__global__ __launch_bounds__(256) void bn_relu_kernel(float* __restrict__ y)
{
    const int i4 = (blockIdx.x * 256 + threadIdx.x) * 4;
    const int ch = (i4 >> 12) & (NO - 1);
    const float sc = g_scF[ch], sh = g_shF[ch];
    float4 v = *(float4*)&y[i4];
    v.x = fmaxf(fmaf(v.x, sc, sh), 0.f);
    v.y = fmaxf(fmaf(v.y, sc, sh), 0.f);
    v.z = fmaxf(fmaf(v.z, sc, sh), 0.f);
    v.w = fmaxf(fmaf(v.w, sc, sh), 0.f);
    *(float4*)&y[i4] = v;
}

// ---------------- launch ----------------
extern "C" void kernel_launch(void* const* d_in, const int* in_sizes, int n_in,
                              void* d_out, int out_size)
{
    (void)in_sizes; (void)n_in; (void)out_size;
    const float* x   = (const float*)d_in[0];
    const float* w1  = (const float*)d_in[1];
    const float* b1  = (const float*)d_in[2];
    const float* g1  = (const float*)d_in[3];
    const float* be1 = (const float*)d_in[4];
    const float* w2  = (const float*)d_in[5];
    const float* b2  = (const float*)d_in[6];
    const float* g2  = (const float*)d_in[7];
    const float* be2 = (const float*)d_in[8];
    const float* wf  = (const float*)d_in[9];
    const float* bf  = (const float*)d_in[10];
    const float* gf  = (const float*)d_in[11];
    const float* bef = (const float*)d_in[12];
    float* out = (float*)d_out;

    cudaFuncSetAttribute(att_kernel, cudaFuncAttributeMaxDynamicSharedMemorySize,
                         ATT_SMEM_BYTES);

    dim3 gg(NL / 64, NO / 64, NB);
    dual_gemm_kernel<<<gg, 256>>>(x, w1, b1, w2, b2);
    bn_stats_kernel<<<NC, 256>>>(0, nullptr, g1, be1);
    bn_stats_kernel<<<NC, 256>>>(1, nullptr, g2, be2);
    att_kernel<<<NB * NC, ATT_THREADS, ATT_SMEM_BYTES>>>(x);
    final_gemm_kernel<<<gg, 256>>>(wf, bf, out);
    bn_stats_kernel<<<NC, 256>>>(2, out, gf, bef);
    bn_relu_kernel<<<(NB * NC * NL) / (256 * 4), 256>>>(out);
}

// round 4
// speedup vs baseline: 1.6455x; 1.5095x over previous
#include <cuda_runtime.h>
#include <cuda_bf16.h>
#include <stdint.h>

#define NB 4
#define NC 256
#define NO 256
#define NL 4096          // H*W
#define NEPS 1e-5f
#define LOG2E 1.4426950408889634f

#define ATT_THREADS 1024
// smem floats: fn 36864 | t12 8712 (66x66 float2) | xs 4356 | gv 4096  = 54028 floats
#define ATT_F_FN   0
#define ATT_F_T12  36864
#define ATT_F_XS   (36864 + 8712)
#define ATT_F_GV   (36864 + 8712 + 4356)
#define ATT_SMEM_BYTES ((36864 + 8712 + 4356 + 4096) * 4)

#define EX2_APPROX(d, a) \
    asm("ex2.approx.ftz.f32 %0, %1;" : "=f"(d) : "f"(a))

// ---- tensor-core helpers (sm_80+ canonical fragments) ----
#define LDSM_X4(r, a) \
    asm volatile("ldmatrix.sync.aligned.m8n8.x4.shared.b16 {%0,%1,%2,%3}, [%4];" \
        : "=r"((r)[0]), "=r"((r)[1]), "=r"((r)[2]), "=r"((r)[3]) : "r"(a))
#define LDSM_X4_T(r, a) \
    asm volatile("ldmatrix.sync.aligned.m8n8.x4.trans.shared.b16 {%0,%1,%2,%3}, [%4];" \
        : "=r"((r)[0]), "=r"((r)[1]), "=r"((r)[2]), "=r"((r)[3]) : "r"(a))
#define MMA_BF16(c, a, b0_, b1_) \
    asm volatile("mma.sync.aligned.m16n8k16.row.col.f32.bf16.bf16.f32 " \
        "{%0,%1,%2,%3}, {%4,%5,%6,%7}, {%8,%9}, {%0,%1,%2,%3};" \
        : "+f"((c)[0]), "+f"((c)[1]), "+f"((c)[2]), "+f"((c)[3]) \
        : "r"((a)[0]), "r"((a)[1]), "r"((a)[2]), "r"((a)[3]), "r"(b0_), "r"(b1_))

__device__ __forceinline__ uint32_t cvta_smem(const void* p) {
    return (uint32_t)__cvta_generic_to_shared(p);
}

// ---------------- scratch (static device globals; no runtime allocs) ----------------
static __device__ float g_y1[NB*NC*NL];
static __device__ float g_y2[NB*NC*NL];
static __device__ float g_pre[NB*NC*NL];
static __device__ float g_sc1[NC], g_sh1[NC];
static __device__ float g_sc2[NC], g_sh2[NC];
static __device__ float g_scF[NO], g_shF[NO];

// ---------------- bf16x3 tensor-core GEMM ----------------
// Y[o,l] = sum_c W[o,c] * X[c,l] + bias[o], fp32 in/out, bf16x3 internally.
// CTA tile: 128(o) x 128(l), K chunks of 32. Rows >= Mhalf route to (W1,bias1,Y1).
#define APAD 40    // A smem row pitch (bf16): conflict-free ldmatrix (20 words/row)
#define BPAD 136   // B smem row pitch (bf16): 68 words/row

__global__ __launch_bounds__(256, 1) void mma_gemm_kernel(
    const float* __restrict__ W0, const float* __restrict__ W1,
    const float* __restrict__ bias0, const float* __restrict__ bias1,
    const float* __restrict__ X,
    float* __restrict__ Y0, float* __restrict__ Y1, int Mhalf)
{
    __shared__ __align__(16) __nv_bfloat16 sAh[128][APAD];
    __shared__ __align__(16) __nv_bfloat16 sAl[128][APAD];
    __shared__ __align__(16) __nv_bfloat16 sBh[32][BPAD];
    __shared__ __align__(16) __nv_bfloat16 sBl[32][BPAD];

    const int tid  = threadIdx.x;
    const int lane = tid & 31;
    const int wid  = tid >> 5;
    const int wm   = wid >> 2;      // 0..1  (64-row warp band)
    const int wn   = wid & 3;       // 0..3  (32-col warp band)
    const int b    = blockIdx.z;
    const int l0   = blockIdx.y * 128;
    const int o0   = blockIdx.x * 128;

    const float* Wm; const float* bi; float* Yb; int row0;
    if (o0 < Mhalf) { Wm = W0; bi = bias0; Yb = Y0; row0 = o0; }
    else            { Wm = W1; bi = bias1; Yb = Y1; row0 = o0 - Mhalf; }
    Wm += (size_t)row0 * NC;
    const float* Xb = X + (size_t)b * NC * NL + l0;
    Yb += ((size_t)b * NO + row0) * NL + l0;

    // staging maps
    const int ar = tid >> 1;              // A row 0..127 (2 threads/row)
    const int ac = (tid & 1) * 4;         // A cols: ac + i*8, 4 floats each
    const int br = tid >> 3;              // B row (k) 0..31
    const int bc = (tid & 7) * 4;         // B cols: bc + i*32

    float4 apf[4], bpf[4];
#pragma unroll
    for (int i = 0; i < 4; i++) {
        apf[i] = *(const float4*)&Wm[(size_t)ar * NC + ac + i * 8];
        bpf[i] = *(const float4*)&Xb[(size_t)br * NL + bc + i * 32];
    }

    float acc[4][4][4];
#pragma unroll
    for (int i = 0; i < 4; i++)
#pragma unroll
        for (int j = 0; j < 4; j++)
#pragma unroll
            for (int r = 0; r < 4; r++) acc[i][j][r] = 0.f;

    // ldmatrix base addresses (lane-dependent parts)
    const int a_row = wm * 64 + (lane & 15);          // + i*16
    const int a_col = (lane >> 4) * 8;                // + h*16
    const uint32_t aAh = cvta_smem(&sAh[a_row][a_col]);
    const uint32_t aAl = cvta_smem(&sAl[a_row][a_col]);
    const int b_row = (lane & 15);                    // + h*16
    const int b_col = wn * 32 + (lane >> 4) * 8;      // + nt*16
    const uint32_t aBh = cvta_smem(&sBh[b_row][b_col]);
    const uint32_t aBl = cvta_smem(&sBl[b_row][b_col]);

#pragma unroll 1
    for (int ch = 0; ch < 8; ch++) {
        // convert + store staged chunk
#pragma unroll
        for (int i = 0; i < 4; i++) {
            const float v[4] = {apf[i].x, apf[i].y, apf[i].z, apf[i].w};
            __nv_bfloat16 h[4]; __nv_bfloat16 lo[4];
#pragma unroll
            for (int q = 0; q < 4; q++) {
                h[q]  = __float2bfloat16(v[q]);
                lo[q] = __float2bfloat16(v[q] - __bfloat162float(h[q]));
            }
            const int c = ac + i * 8;
            *(__nv_bfloat162*)&sAh[ar][c]     = __halves2bfloat162(h[0], h[1]);
            *(__nv_bfloat162*)&sAh[ar][c + 2] = __halves2bfloat162(h[2], h[3]);
            *(__nv_bfloat162*)&sAl[ar][c]     = __halves2bfloat162(lo[0], lo[1]);
            *(__nv_bfloat162*)&sAl[ar][c + 2] = __halves2bfloat162(lo[2], lo[3]);
        }
#pragma unroll
        for (int i = 0; i < 4; i++) {
            const float v[4] = {bpf[i].x, bpf[i].y, bpf[i].z, bpf[i].w};
            __nv_bfloat16 h[4]; __nv_bfloat16 lo[4];
#pragma unroll
            for (int q = 0; q < 4; q++) {
                h[q]  = __float2bfloat16(v[q]);
                lo[q] = __float2bfloat16(v[q] - __bfloat162float(h[q]));
            }
            const int c = bc + i * 32;
            *(__nv_bfloat162*)&sBh[br][c]     = __halves2bfloat162(h[0], h[1]);
            *(__nv_bfloat162*)&sBh[br][c + 2] = __halves2bfloat162(h[2], h[3]);
            *(__nv_bfloat162*)&sBl[br][c]     = __halves2bfloat162(lo[0], lo[1]);
            *(__nv_bfloat162*)&sBl[br][c + 2] = __halves2bfloat162(lo[2], lo[3]);
        }
        __syncthreads();

        if (ch < 7) {
            const int k0 = (ch + 1) * 32;
#pragma unroll
            for (int i = 0; i < 4; i++) {
                apf[i] = *(const float4*)&Wm[(size_t)ar * NC + k0 + ac + i * 8];
                bpf[i] = *(const float4*)&Xb[(size_t)(k0 + br) * NL + bc + i * 32];
            }
        }

#pragma unroll
        for (int h = 0; h < 2; h++) {
            uint32_t bh[8], bl[8];
#pragma unroll
            for (int nt = 0; nt < 2; nt++) {
                const uint32_t off = (uint32_t)((h * 16) * BPAD + nt * 16) * 2;
                LDSM_X4_T(&bh[nt * 4], aBh + off);
                LDSM_X4_T(&bl[nt * 4], aBl + off);
            }
#pragma unroll
            for (int i = 0; i < 4; i++) {
                uint32_t ah[4], al[4];
                const uint32_t off = (uint32_t)((i * 16) * APAD + h * 16) * 2;
                LDSM_X4(ah, aAh + off);
                LDSM_X4(al, aAl + off);
#pragma unroll
                for (int j = 0; j < 4; j++) {
                    MMA_BF16(acc[i][j], ah, bh[j * 2], bh[j * 2 + 1]);
                    MMA_BF16(acc[i][j], ah, bl[j * 2], bl[j * 2 + 1]);
                    MMA_BF16(acc[i][j], al, bh[j * 2], bh[j * 2 + 1]);
                }
            }
        }
        __syncthreads();
    }

    // epilogue: d0,d1 -> row g, cols tig*2..+1 ; d2,d3 -> row g+8
    const int g   = lane >> 2;
    const int tig = lane & 3;
#pragma unroll
    for (int i = 0; i < 4; i++) {
        const int r0  = wm * 64 + i * 16 + g;
        const float bi0 = bi[row0 * 0 + r0 + 0];   // bias of global row row0+r0
        const float bi8 = bi[r0 + 8];
        float* y0 = Yb + (size_t)r0 * NL + wn * 32 + tig * 2;
        float* y8 = y0 + (size_t)8 * NL;
#pragma unroll
        for (int j = 0; j < 4; j++) {
            *(float2*)&y0[j * 8] = make_float2(acc[i][j][0] + bi0, acc[i][j][1] + bi0);
            *(float2*)&y8[j * 8] = make_float2(acc[i][j][2] + bi8, acc[i][j][3] + bi8);
        }
    }
}

// ---------------- BN stats: per-channel mean/var over (B,H,W) -> scale/shift --------
__global__ __launch_bounds__(256) void bn_stats_kernel(
    int sel, const float* __restrict__ yext,
    const float* __restrict__ gw, const float* __restrict__ bw)
{
    const float* y = (sel == 0) ? g_y1 : (sel == 1) ? g_y2 : yext;
    float* sc = (sel == 0) ? g_sc1 : (sel == 1) ? g_sc2 : g_scF;
    float* sh = (sel == 0) ? g_sh1 : (sel == 1) ? g_sh2 : g_shF;
    const int ch = blockIdx.x;
    float s = 0.f, s2 = 0.f;
    for (int i = threadIdx.x; i < NB * NL; i += 256) {
        int b = i >> 12, l = i & (NL - 1);
        float v = y[((size_t)b * NC + ch) * NL + l];
        s += v; s2 += v * v;
    }
    __shared__ float r1[256], r2[256];
    r1[threadIdx.x] = s; r2[threadIdx.x] = s2;
    __syncthreads();
    for (int st = 128; st > 0; st >>= 1) {
        if (threadIdx.x < st) {
            r1[threadIdx.x] += r1[threadIdx.x + st];
            r2[threadIdx.x] += r2[threadIdx.x + st];
        }
        __syncthreads();
    }
    if (threadIdx.x == 0) {
        const float inv = 1.f / (float)(NB * NL);
        float mu  = r1[0] * inv;
        float var = r2[0] * inv - mu * mu;
        float r   = rsqrtf(var + NEPS) * gw[ch];
        sc[ch] = r;
        sh[ch] = bw[ch] - mu * r;
    }
}

// ---------------- scrambled-unfold attention (padded halo planes) --------------------
__global__ __launch_bounds__(ATT_THREADS) void att_kernel(const float* __restrict__ x)
{
    extern __shared__ float sm[];
    float* fn  = sm + ATT_F_FN;    // 36864 numerators e * xu
    float* t12 = sm + ATT_F_T12;   // 66x66 interleaved (tri1, tri2) float2
    float* xs  = sm + ATT_F_XS;    // 66x66 padded x plane
    float* gv  = sm + ATT_F_GV;    // 4096 per-group 1/sum

    const int bc = blockIdx.x;          // b*NC + c
    const int c  = bc & (NC - 1);
    const size_t base = (size_t)bc * NL;
    const float sc1 = g_sc1[c], sh1 = g_sh1[c];
    const float sc2 = g_sc2[c], sh2 = g_sh2[c];

    for (int i = threadIdx.x; i < 4356; i += ATT_THREADS) xs[i] = 0.f;
    for (int i = threadIdx.x; i < 8712; i += ATT_THREADS) t12[i] = 0.f;
    __syncthreads();

    for (int l4 = threadIdx.x * 4; l4 < NL; l4 += ATT_THREADS * 4) {
        float4 xv = *(const float4*)&x[base + l4];
        float4 a  = *(const float4*)&g_y1[base + l4];
        float4 q  = *(const float4*)&g_y2[base + l4];
        const int pidx = (l4 >> 6) * 66 + (l4 & 63) + 67;
        xs[pidx+0] = xv.x; xs[pidx+1] = xv.y; xs[pidx+2] = xv.z; xs[pidx+3] = xv.w;
        float t1v[4] = {
            fmaxf(fmaf(a.x, sc1, sh1), 0.f), fmaxf(fmaf(a.y, sc1, sh1), 0.f),
            fmaxf(fmaf(a.z, sc1, sh1), 0.f), fmaxf(fmaf(a.w, sc1, sh1), 0.f) };
        float t2v[4] = {
            fmaxf(fmaf(q.x, sc2, sh2), 0.f), fmaxf(fmaf(q.y, sc2, sh2), 0.f),
            fmaxf(fmaf(q.z, sc2, sh2), 0.f), fmaxf(fmaf(q.w, sc2, sh2), 0.f) };
#pragma unroll
        for (int j = 0; j < 4; j++)
            *(float2*)&t12[2 * (pidx + j)] = make_float2(t1v[j], t2v[j]);
    }
    __syncthreads();

    for (int g = threadIdx.x; g < NL; g += ATT_THREADS) {
        const int n0 = 9 * g;
        const int p0 = n0 >> 12;
        const int l0 = n0 & (NL - 1);
        const int di0 = (p0 * 171) >> 9, dj0 = p0 - 3 * di0;
        const int p1 = p0 + 1;
        const int di1 = (p1 * 171) >> 9, dj1 = p1 - 3 * di1;
        const int C0 = di0 * 66 + dj0;
        const int C1 = di1 * 66 + dj1 - 4224;
        float ku[9], qu[9], xv[9];
#pragma unroll
        for (int r = 0; r < 9; r++) {
            const int l = l0 + r;
            const int C = (l >> 12) ? C1 : C0;
            const int idx = (l >> 6) * 66 + (l & 63) + C;
            const float2 kq = *(const float2*)&t12[2 * idx];
            ku[r] = kq.x; qu[r] = kq.y;
            xv[r] = xs[idx];
        }
        const float quC = qu[4] * LOG2E;
        const float kuC = ku[4] * LOG2E;
        float lg[9];
        float m = -1e30f;
#pragma unroll
        for (int r = 0; r < 9; r++) {
            lg[r] = fmaf(ku[r], quC, kuC * qu[r]);
            m = fmaxf(m, lg[r]);
        }
        float s = 0.f;
#pragma unroll
        for (int r = 0; r < 9; r++) {
            float e; EX2_APPROX(e, lg[r] - m);
            s += e;
            fn[n0 + r] = e * xv[r];
        }
        gv[g] = 1.f / s;
    }
    __syncthreads();

    for (int l = threadIdx.x; l < NL; l += ATT_THREADS) {
        float acc = 0.f;
#pragma unroll
        for (int p = 0; p < 9; p++) {
            const unsigned n = (p << 12) + l;
            const unsigned gidx = __umulhi(n, 0x38E38E39u) >> 1;   // n/9
            acc += fn[n] * gv[gidx];
        }
        g_pre[base + l] = acc;
    }
}

// ---------------- final in-place BN + ReLU on d_out ----------------
__global__ __launch_bounds__(256) void bn_relu_kernel(float* __restrict__ y)
{
    const int i4 = (blockIdx.x * 256 + threadIdx.x) * 4;
    const int ch = (i4 >> 12) & (NO - 1);
    const float sc = g_scF[ch], sh = g_shF[ch];
    float4 v = *(float4*)&y[i4];
    v.x = fmaxf(fmaf(v.x, sc, sh), 0.f);
    v.y = fmaxf(fmaf(v.y, sc, sh), 0.f);
    v.z = fmaxf(fmaf(v.z, sc, sh), 0.f);
    v.w = fmaxf(fmaf(v.w, sc, sh), 0.f);
    *(float4*)&y[i4] = v;
}

// ---------------- launch ----------------
extern "C" void kernel_launch(void* const* d_in, const int* in_sizes, int n_in,
                              void* d_out, int out_size)
{
    (void)in_sizes; (void)n_in; (void)out_size;
    const float* x   = (const float*)d_in[0];
    const float* w1  = (const float*)d_in[1];
    const float* b1  = (const float*)d_in[2];
    const float* g1  = (const float*)d_in[3];
    const float* be1 = (const float*)d_in[4];
    const float* w2  = (const float*)d_in[5];
    const float* b2  = (const float*)d_in[6];
    const float* g2  = (const float*)d_in[7];
    const float* be2 = (const float*)d_in[8];
    const float* wf  = (const float*)d_in[9];
    const float* bf  = (const float*)d_in[10];
    const float* gf  = (const float*)d_in[11];
    const float* bef = (const float*)d_in[12];
    float* out = (float*)d_out;

    cudaFuncSetAttribute(att_kernel, cudaFuncAttributeMaxDynamicSharedMemorySize,
                         ATT_SMEM_BYTES);

    float* g_y1p; cudaGetSymbolAddress((void**)&g_y1p, g_y1);
    float* g_y2p; cudaGetSymbolAddress((void**)&g_y2p, g_y2);
    float* g_prep; cudaGetSymbolAddress((void**)&g_prep, g_pre);

    // dual GEMM: stacked M=512 (rows 0-255 -> w1/y1, 256-511 -> w2/y2)
    dim3 gd(4, NL / 128, NB);
    mma_gemm_kernel<<<gd, 256>>>(w1, w2, b1, b2, x, g_y1p, g_y2p, 256);
    bn_stats_kernel<<<NC, 256>>>(0, nullptr, g1, be1);
    bn_stats_kernel<<<NC, 256>>>(1, nullptr, g2, be2);
    att_kernel<<<NB * NC, ATT_THREADS, ATT_SMEM_BYTES>>>(x);
    // final GEMM: M=256 single matrix
    dim3 gf2(2, NL / 128, NB);
    mma_gemm_kernel<<<gf2, 256>>>(wf, wf, bf, bf, g_prep, out, out, 512);
    bn_stats_kernel<<<NC, 256>>>(2, out, gf, bef);
    bn_relu_kernel<<<(NB * NC * NL) / (256 * 4), 256>>>(out);
}